// round 3
// baseline (speedup 1.0000x reference)
#include <cuda_runtime.h>

// Shapes (fixed for this problem)
#define LSEQ 512
#define CIN  256
#define HID  32
#define PAIR 64

// Scratch (static __device__ arrays — no allocation allowed)
__device__ float g_s[LSEQ * HID];            // s[i][h]
__device__ float g_tmp[LSEQ * PAIR * HID];   // tmp[i][k][c]

// ---- packed f32x2 helpers (Blackwell FFMA2) ----
static __device__ __forceinline__ unsigned long long pk2(float a, float b) {
    unsigned long long r;
    asm("mov.b64 %0, {%1, %2};" : "=l"(r) : "f"(a), "f"(b));
    return r;
}
static __device__ __forceinline__ void upk2(unsigned long long v, float& a, float& b) {
    asm("mov.b64 {%0, %1}, %2;" : "=f"(a), "=f"(b) : "l"(v));
}
static __device__ __forceinline__ unsigned long long ffma2(
    unsigned long long a, unsigned long long b, unsigned long long c) {
    unsigned long long r;
    asm("fma.rn.f32x2 %0, %1, %2, %3;" : "=l"(r) : "l"(a), "l"(b), "l"(c));
    return r;
}

// ============================================================
// K12 (fused): per block of 8 i-rows:
//   part 1: s[i][h] = dot(seq[i,:], W1[h,:]) + b1[h]   (kept in smem + g_s)
//   part 2: tmp[i][k][c] = sum_d s[i][d] * W2[k*32+c][d]
// ============================================================
__global__ __launch_bounds__(256) void k12_fused(
    const float* __restrict__ seq, const float* __restrict__ W1,
    const float* __restrict__ b1, const float* __restrict__ W2)
{
    __shared__ float seq_s[8 * CIN];     // 8 KB
    __shared__ float w1t[CIN * HID];     // 32 KB, [d][h]
    __shared__ float s8[8 * HID];        // 1 KB
    int tid = threadIdx.x;
    int i0 = blockIdx.x * 8;

    // stage seq rows (coalesced float4)
    const float4* sg = (const float4*)(seq + (size_t)i0 * CIN);
    float4* ss4 = (float4*)seq_s;
    #pragma unroll
    for (int t = tid; t < 8 * CIN / 4; t += 256) ss4[t] = sg[t];

    // stage W1 transposed [d][h]
    const float4* wg = (const float4*)W1;
    #pragma unroll
    for (int t = tid; t < HID * CIN / 4; t += 256) {
        int h = t & 31, d4 = t >> 5;
        float4 v = wg[h * (CIN / 4) + d4];
        w1t[(d4 * 4 + 0) * HID + h] = v.x;
        w1t[(d4 * 4 + 1) * HID + h] = v.y;
        w1t[(d4 * 4 + 2) * HID + h] = v.z;
        w1t[(d4 * 4 + 3) * HID + h] = v.w;
    }
    __syncthreads();

    // part 1: one (i, h) per thread; float4 broadcast on the seq side
    {
        int i = tid >> 5, h = tid & 31;
        float acc = b1[h];
        const float4* sv4 = (const float4*)(seq_s + i * CIN);
        #pragma unroll 16
        for (int d4 = 0; d4 < CIN / 4; d4++) {
            float4 sv = sv4[d4];
            acc += sv.x * w1t[(d4 * 4 + 0) * HID + h];
            acc += sv.y * w1t[(d4 * 4 + 1) * HID + h];
            acc += sv.z * w1t[(d4 * 4 + 2) * HID + h];
            acc += sv.w * w1t[(d4 * 4 + 3) * HID + h];
        }
        s8[tid] = acc;
        g_s[(size_t)i0 * HID + tid] = acc;
    }
    __syncthreads();

    // part 2: tmp. kc = k*32 + c; W2 linear index kc*32 + d.
    const float4* s84 = (const float4*)s8;
    #pragma unroll
    for (int p = 0; p < 8; p++) {
        int kc = tid + p * 256;                  // 0..2047
        const float4* wr = (const float4*)(W2 + (size_t)kc * 32);
        float4 w[8];
        #pragma unroll
        for (int q = 0; q < 8; q++) w[q] = wr[q];
        #pragma unroll
        for (int i = 0; i < 8; i++) {
            float acc = 0.f;
            #pragma unroll
            for (int q = 0; q < 8; q++) {
                float4 sv = s84[i * 8 + q];      // warp-uniform -> smem broadcast
                acc += sv.x * w[q].x + sv.y * w[q].y + sv.z * w[q].z + sv.w * w[q].w;
            }
            g_tmp[(size_t)(i0 + i) * 2048 + kc] = acc;
        }
    }
}

// ============================================================
// K3 (dominant): out[i][j][k] = sum_c tmp[i][k][c]*s[j][c] + b2[k] + pair[i][j][k]
// grid (2, 512): blockIdx.y = i, blockIdx.x = j-tile of 256.
// pair_rep tile (64 KB, contiguous) prefetched into smem via cp.async at block
// start, overlapping the whole compute loop. Dynamic smem = 104 KB, 2 blocks/SM.
// ============================================================
__global__ __launch_bounds__(256, 2) void k3_main(
    const float* __restrict__ pair_rep, const float* __restrict__ b2,
    float* __restrict__ out)
{
    extern __shared__ float dyn[];
    float* pair_sm = dyn;                 // 256*64      = 16384 f (64 KB)
    float* s_sm    = dyn + 16384;         // [c][j] 32*256 = 8192 f (32 KB)
    float* tmp_sm  = dyn + 16384 + 8192;  // [c][k] 32*64  = 2048 f (8 KB)

    int tid = threadIdx.x;
    int i  = blockIdx.y;
    int jt = blockIdx.x;

    // ---- async prefetch of the pair tile (fire & forget until epilogue) ----
    {
        const float4* psrc = (const float4*)(pair_rep + (((size_t)i * 512 + (size_t)jt * 256) * 64));
        unsigned int pdst = (unsigned int)__cvta_generic_to_shared(pair_sm);
        #pragma unroll
        for (int q = 0; q < 16; q++) {
            int t = tid + q * 256;
            asm volatile("cp.async.cg.shared.global [%0], [%1], 16;"
                         :: "r"(pdst + t * 16), "l"(psrc + t));
        }
        asm volatile("cp.async.commit_group;");
    }

    // ---- stage tmp[i] transposed [c][k] ----
    if (tid < 64) {
        const float4* tr = (const float4*)(g_tmp + (size_t)i * 2048 + (size_t)tid * 32);
        #pragma unroll
        for (int q = 0; q < 8; q++) {
            float4 v = tr[q];
            tmp_sm[(q * 4 + 0) * 64 + tid] = v.x;
            tmp_sm[(q * 4 + 1) * 64 + tid] = v.y;
            tmp_sm[(q * 4 + 2) * 64 + tid] = v.z;
            tmp_sm[(q * 4 + 3) * 64 + tid] = v.w;
        }
    }
    // ---- stage s tile transposed [c][j] ----
    {
        const float4* sr = (const float4*)(g_s + (size_t)(jt * 256 + tid) * 32);
        #pragma unroll
        for (int q = 0; q < 8; q++) {
            float4 v = sr[q];
            s_sm[(q * 4 + 0) * 256 + tid] = v.x;
            s_sm[(q * 4 + 1) * 256 + tid] = v.y;
            s_sm[(q * 4 + 2) * 256 + tid] = v.z;
            s_sm[(q * 4 + 3) * 256 + tid] = v.w;
        }
    }
    __syncthreads();

    int tk = tid & 7;        // k = tk*8 .. tk*8+7
    int tj = tid >> 3;       // j = jt*256 + tj*8 .. +7

    unsigned long long acc[8][4];
    #pragma unroll
    for (int a = 0; a < 8; a++)
        #pragma unroll
        for (int b = 0; b < 4; b++) acc[a][b] = 0ull;

    const float4* t4 = (const float4*)tmp_sm;   // row = 16 float4
    const float4* s4 = (const float4*)s_sm;     // row = 64 float4

    #pragma unroll 4
    for (int c = 0; c < 32; c++) {
        float4 ta = t4[c * 16 + tk * 2];
        float4 tb = t4[c * 16 + tk * 2 + 1];
        unsigned long long tp0 = pk2(ta.x, ta.y);
        unsigned long long tp1 = pk2(ta.z, ta.w);
        unsigned long long tp2 = pk2(tb.x, tb.y);
        unsigned long long tp3 = pk2(tb.z, tb.w);
        float4 sa = s4[c * 64 + tj * 2];
        float4 sb = s4[c * 64 + tj * 2 + 1];
        float sv[8] = {sa.x, sa.y, sa.z, sa.w, sb.x, sb.y, sb.z, sb.w};
        #pragma unroll
        for (int jj = 0; jj < 8; jj++) {
            unsigned long long sd = pk2(sv[jj], sv[jj]);
            acc[jj][0] = ffma2(sd, tp0, acc[jj][0]);
            acc[jj][1] = ffma2(sd, tp1, acc[jj][1]);
            acc[jj][2] = ffma2(sd, tp2, acc[jj][2]);
            acc[jj][3] = ffma2(sd, tp3, acc[jj][3]);
        }
    }

    // ---- wait for the pair tile, then fused epilogue ----
    asm volatile("cp.async.wait_group 0;");
    __syncthreads();

    const float4* b24 = (const float4*)b2;
    float4 bz0 = b24[tk * 2], bz1 = b24[tk * 2 + 1];
    const float4* pr4 = (const float4*)pair_sm;
    #pragma unroll
    for (int jj = 0; jj < 8; jj++) {
        int jloc = tj * 8 + jj;
        int poff = jloc * 16 + tk * 2;           // float4 units within tile
        float4 p0 = pr4[poff], p1 = pr4[poff + 1];
        float x0, x1, x2, x3, x4, x5, x6, x7;
        upk2(acc[jj][0], x0, x1);
        upk2(acc[jj][1], x2, x3);
        upk2(acc[jj][2], x4, x5);
        upk2(acc[jj][3], x6, x7);
        float4 o0 = make_float4(x0 + p0.x + bz0.x, x1 + p0.y + bz0.y,
                                x2 + p0.z + bz0.z, x3 + p0.w + bz0.w);
        float4 o1 = make_float4(x4 + p1.x + bz1.x, x5 + p1.y + bz1.y,
                                x6 + p1.z + bz1.z, x7 + p1.w + bz1.w);
        size_t off = (((size_t)i * 512 + (size_t)(jt * 256 + jloc)) * 64) + (size_t)tk * 8;
        float4* orow = (float4*)(out + off);
        orow[0] = o0;
        orow[1] = o1;
    }
}

// ============================================================
// Launch. Inputs in metadata order:
//   0 seq_rep [1,512,256] f32
//   1 pair_rep [1,512,512,64] f32
//   2 W1 [32,256] f32
//   3 b1 [32] f32
//   4 W2 [64,1024] f32
//   5 b2 [64] f32
// out: [1,512,512,64] f32
// ============================================================
extern "C" void kernel_launch(void* const* d_in, const int* in_sizes, int n_in,
                              void* d_out, int out_size)
{
    const float* seq  = (const float*)d_in[0];
    const float* pair = (const float*)d_in[1];
    const float* W1   = (const float*)d_in[2];
    const float* b1   = (const float*)d_in[3];
    const float* W2   = (const float*)d_in[4];
    const float* b2   = (const float*)d_in[5];
    float* out = (float*)d_out;

    // Unconditional (idempotent, no static guards per harness rules).
    const int k3_smem = (16384 + 8192 + 2048) * 4;   // 104 KB
    cudaFuncSetAttribute(k3_main, cudaFuncAttributeMaxDynamicSharedMemorySize, k3_smem);

    k12_fused<<<LSEQ / 8, 256>>>(seq, W1, b1, W2);
    dim3 g3(2, LSEQ);
    k3_main<<<g3, 256, k3_smem>>>(pair, b2, out);
}

// round 4
// speedup vs baseline: 1.1642x; 1.1642x over previous
#include <cuda_runtime.h>

#define LSEQ 512
#define CIN  256
#define HID  32
#define PAIR 64

__device__ float g_s[LSEQ * HID];            // s[i][h]
__device__ float g_tmp[LSEQ * PAIR * HID];   // tmp[i][k*32+c]

// ---- packed f32x2 helpers (Blackwell FFMA2) ----
static __device__ __forceinline__ unsigned long long pk2(float a, float b) {
    unsigned long long r;
    asm("mov.b64 %0, {%1, %2};" : "=l"(r) : "f"(a), "f"(b));
    return r;
}
static __device__ __forceinline__ void upk2(unsigned long long v, float& a, float& b) {
    asm("mov.b64 {%0, %1}, %2;" : "=f"(a), "=f"(b) : "l"(v));
}
static __device__ __forceinline__ unsigned long long ffma2(
    unsigned long long a, unsigned long long b, unsigned long long c) {
    unsigned long long r;
    asm("fma.rn.f32x2 %0, %1, %2, %3;" : "=l"(r) : "l"(a), "l"(b), "l"(c));
    return r;
}

// ============================================================
// K1: s[i][h] = dot(seq[i,:], W1[h,:]) + b1[h]
// 512 blocks (one per i), 256 threads: h = t>>3, 8 lanes per h each
// covering 32 d's; shfl-xor reduce within the 8-lane group.
// ============================================================
__global__ __launch_bounds__(256) void k1_s(
    const float* __restrict__ seq, const float* __restrict__ W1,
    const float* __restrict__ b1)
{
    int i = blockIdx.x;
    int t = threadIdx.x;
    int h = t >> 3, sub = t & 7;
    const float4* sr = (const float4*)(seq + (size_t)i * CIN) + sub * 8;
    const float4* wr = (const float4*)(W1 + (size_t)h * CIN) + sub * 8;
    float acc = 0.f;
    #pragma unroll
    for (int q = 0; q < 8; q++) {
        float4 a = sr[q], b = wr[q];
        acc += a.x * b.x + a.y * b.y + a.z * b.z + a.w * b.w;
    }
    acc += __shfl_xor_sync(0xffffffffu, acc, 1);
    acc += __shfl_xor_sync(0xffffffffu, acc, 2);
    acc += __shfl_xor_sync(0xffffffffu, acc, 4);
    if (sub == 0) g_s[(size_t)i * HID + h] = acc + b1[h];
}

// ============================================================
// K2: tmp[i][kc] = sum_d s[i][d] * W2[kc*32+d],  kc = k*32 + c.
// grid (4 kc-quarters, 64 i-groups of 8), 256 threads; each thread
// handles 2 kc rows x 8 i. W2 rows stay in registers across the 8 i.
// ============================================================
__global__ __launch_bounds__(256) void k2_tmp(const float* __restrict__ W2)
{
    __shared__ float s8[8 * HID];   // 1 KB
    int tid = threadIdx.x;
    int i0  = blockIdx.y * 8;
    int kc0 = blockIdx.x * 512;
    s8[tid] = g_s[(size_t)i0 * HID + tid];
    __syncthreads();

    const float4* s84 = (const float4*)s8;
    #pragma unroll
    for (int p = 0; p < 2; p++) {
        int kc = kc0 + tid + p * 256;
        const float4* wr = (const float4*)(W2 + (size_t)kc * 32);
        float4 w[8];
        #pragma unroll
        for (int q = 0; q < 8; q++) w[q] = wr[q];
        #pragma unroll
        for (int i = 0; i < 8; i++) {
            float acc = 0.f;
            #pragma unroll
            for (int q = 0; q < 8; q++) {
                float4 sv = s84[i * 8 + q];   // warp-uniform -> broadcast
                acc += sv.x * w[q].x + sv.y * w[q].y + sv.z * w[q].z + sv.w * w[q].w;
            }
            g_tmp[(size_t)(i0 + i) * 2048 + kc] = acc;
        }
    }
}

// ============================================================
// K3: out[i][j][k] = sum_c tmp[i][k][c]*s[j][c] + b2[k] + pair[i][j][k]
// grid (4, 512): blockIdx.y = i, blockIdx.x = jt (j-tile of 128).
// 128 threads; smem = pair 32K + s 16K + tmp 8K = 56 KB -> 4 blocks/SM.
// Order: staging LDGs FIRST, then cp.async pair prefetch (L1tex FIFO),
// STS, sync, compute, wait, fused epilogue.
// Split-k mapping: thread (tk) owns k in {tk*4..+3} u {32+tk*4..+3} so
// every LDS.128 has idx%8 == tk (conflict-free).
// ============================================================
__global__ __launch_bounds__(128, 4) void k3_main(
    const float* __restrict__ pair_rep, const float* __restrict__ b2,
    float* __restrict__ out)
{
    extern __shared__ float dyn[];
    float* pair_sm = dyn;                  // 128*64 = 8192 f (32 KB)
    float* s_sm    = dyn + 8192;           // [c][j] 32*128 = 4096 f (16 KB)
    float* tmp_sm  = dyn + 8192 + 4096;    // [c][k] 32*64  = 2048 f (8 KB)

    int tid = threadIdx.x;
    int i  = blockIdx.y;
    int jt = blockIdx.x;

    // ---- phase 1: issue staging LDGs (before cp.async: L1tex FIFO) ----
    float4 sreg[8];
    {
        const float4* sr = (const float4*)(g_s + (size_t)(jt * 128 + tid) * 32);
        #pragma unroll
        for (int q = 0; q < 8; q++) sreg[q] = sr[q];
    }
    float4 treg[8];
    if (tid < 64) {
        const float4* tr = (const float4*)(g_tmp + (size_t)i * 2048 + (size_t)tid * 32);
        #pragma unroll
        for (int q = 0; q < 8; q++) treg[q] = tr[q];
    }

    // ---- phase 2: async pair tile prefetch (fire & forget) ----
    {
        const float4* psrc = (const float4*)(pair_rep + (((size_t)i * 512 + (size_t)jt * 128) * 64));
        unsigned int pdst = (unsigned int)__cvta_generic_to_shared(pair_sm);
        #pragma unroll
        for (int q = 0; q < 16; q++) {
            int t = tid + q * 128;
            asm volatile("cp.async.cg.shared.global [%0], [%1], 16;"
                         :: "r"(pdst + t * 16), "l"(psrc + t));
        }
        asm volatile("cp.async.commit_group;");
    }

    // ---- phase 3: STS transposed staging ----
    #pragma unroll
    for (int q = 0; q < 8; q++) {
        s_sm[(q * 4 + 0) * 128 + tid] = sreg[q].x;
        s_sm[(q * 4 + 1) * 128 + tid] = sreg[q].y;
        s_sm[(q * 4 + 2) * 128 + tid] = sreg[q].z;
        s_sm[(q * 4 + 3) * 128 + tid] = sreg[q].w;
    }
    if (tid < 64) {
        #pragma unroll
        for (int q = 0; q < 8; q++) {
            tmp_sm[(q * 4 + 0) * 64 + tid] = treg[q].x;
            tmp_sm[(q * 4 + 1) * 64 + tid] = treg[q].y;
            tmp_sm[(q * 4 + 2) * 64 + tid] = treg[q].z;
            tmp_sm[(q * 4 + 3) * 64 + tid] = treg[q].w;
        }
    }
    __syncthreads();

    int tk = tid & 7;        // owns k = tk*4..+3 and 32+tk*4..+3
    int tj = tid >> 3;       // owns j = jt*128 + tj*8 .. +7

    unsigned long long acc[8][4];
    #pragma unroll
    for (int a = 0; a < 8; a++)
        #pragma unroll
        for (int b = 0; b < 4; b++) acc[a][b] = 0ull;

    const float4* t4 = (const float4*)tmp_sm;   // row = 16 float4
    const float4* s4 = (const float4*)s_sm;     // row = 32 float4

    #pragma unroll 4
    for (int c = 0; c < 32; c++) {
        float4 ta = t4[c * 16 + tk];            // k = tk*4..+3
        float4 tb = t4[c * 16 + 8 + tk];        // k = 32+tk*4..+3
        unsigned long long tp0 = pk2(ta.x, ta.y);
        unsigned long long tp1 = pk2(ta.z, ta.w);
        unsigned long long tp2 = pk2(tb.x, tb.y);
        unsigned long long tp3 = pk2(tb.z, tb.w);
        float4 sa = s4[c * 32 + tj * 2];
        float4 sb = s4[c * 32 + tj * 2 + 1];
        float sv[8] = {sa.x, sa.y, sa.z, sa.w, sb.x, sb.y, sb.z, sb.w};
        #pragma unroll
        for (int jj = 0; jj < 8; jj++) {
            unsigned long long sd = pk2(sv[jj], sv[jj]);
            acc[jj][0] = ffma2(sd, tp0, acc[jj][0]);
            acc[jj][1] = ffma2(sd, tp1, acc[jj][1]);
            acc[jj][2] = ffma2(sd, tp2, acc[jj][2]);
            acc[jj][3] = ffma2(sd, tp3, acc[jj][3]);
        }
    }

    // ---- wait for the pair tile, fused epilogue ----
    asm volatile("cp.async.wait_group 0;");
    __syncthreads();

    const float4* b24 = (const float4*)b2;
    float4 bz0 = b24[tk], bz1 = b24[8 + tk];
    const float4* pr4 = (const float4*)pair_sm;
    #pragma unroll
    for (int jj = 0; jj < 8; jj++) {
        int jloc = tj * 8 + jj;
        float4 p0 = pr4[jloc * 16 + tk];        // idx%8 == tk -> conflict-free
        float4 p1 = pr4[jloc * 16 + 8 + tk];
        float x0, x1, x2, x3, x4, x5, x6, x7;
        upk2(acc[jj][0], x0, x1);
        upk2(acc[jj][1], x2, x3);
        upk2(acc[jj][2], x4, x5);
        upk2(acc[jj][3], x6, x7);
        float4 o0 = make_float4(x0 + p0.x + bz0.x, x1 + p0.y + bz0.y,
                                x2 + p0.z + bz0.z, x3 + p0.w + bz0.w);
        float4 o1 = make_float4(x4 + p1.x + bz1.x, x5 + p1.y + bz1.y,
                                x6 + p1.z + bz1.z, x7 + p1.w + bz1.w);
        size_t base = (((size_t)i * 512 + (size_t)(jt * 128 + jloc)) * 64);
        float4* op = (float4*)(out + base);
        op[tk] = o0;           // floats [tk*4 .. +3]
        op[8 + tk] = o1;       // floats [32+tk*4 .. +3]
    }
}

// ============================================================
// Launch. Inputs (metadata order): seq, pair_rep, W1, b1, W2, b2.
// ============================================================
extern "C" void kernel_launch(void* const* d_in, const int* in_sizes, int n_in,
                              void* d_out, int out_size)
{
    const float* seq  = (const float*)d_in[0];
    const float* pair = (const float*)d_in[1];
    const float* W1   = (const float*)d_in[2];
    const float* b1   = (const float*)d_in[3];
    const float* W2   = (const float*)d_in[4];
    const float* b2   = (const float*)d_in[5];
    float* out = (float*)d_out;

    const int k3_smem = (8192 + 4096 + 2048) * 4;   // 56 KB
    cudaFuncSetAttribute(k3_main, cudaFuncAttributeMaxDynamicSharedMemorySize, k3_smem);

    k1_s<<<LSEQ, 256>>>(seq, W1, b1);
    dim3 g2(4, 64);
    k2_tmp<<<g2, 256>>>(W2);
    dim3 g3(4, LSEQ);
    k3_main<<<g3, 128, k3_smem>>>(pair, b2, out);
}

// round 5
// speedup vs baseline: 1.2507x; 1.0743x over previous
#include <cuda_runtime.h>

#define LSEQ 512
#define CIN  256
#define HID  32
#define PAIR 64

__device__ float g_s[LSEQ * HID];            // s[i][h]
__device__ float g_tmp[LSEQ * PAIR * HID];   // tmp[i][k*32+c]

// ---- packed f32x2 helpers (Blackwell FFMA2) ----
static __device__ __forceinline__ unsigned long long pk2(float a, float b) {
    unsigned long long r;
    asm("mov.b64 %0, {%1, %2};" : "=l"(r) : "f"(a), "f"(b));
    return r;
}
static __device__ __forceinline__ void upk2(unsigned long long v, float& a, float& b) {
    asm("mov.b64 {%0, %1}, %2;" : "=f"(a), "=f"(b) : "l"(v));
}
static __device__ __forceinline__ unsigned long long ffma2(
    unsigned long long a, unsigned long long b, unsigned long long c) {
    unsigned long long r;
    asm("fma.rn.f32x2 %0, %1, %2, %3;" : "=l"(r) : "l"(a), "l"(b), "l"(c));
    return r;
}

// ============================================================
// K2 (fused s + tmp): grid (4 kc-quarters, 64 i-groups), 256 threads.
//  part 0: stage W1 transposed [d][h] (stride 33 to kill bank conflicts),
//          stage 8 seq rows.
//  part 1: s8[i][h] = dot(seq[i,:], W1[h,:]) + b1[h]
//          (warp w -> i=w, lane -> h; seq side is uniform broadcast,
//           W1 side LDS banks (4*d4+h)%32 distinct per lane).
//          bx==0 blocks also publish g_s for k3.
//  part 2: tmp[i][kc] = sum_d s8[i][d] * W2[kc*32+d]; W2 rows live in
//          registers across the 8 i.
// ============================================================
__global__ __launch_bounds__(256) void k2_fused(
    const float* __restrict__ seq, const float* __restrict__ W1,
    const float* __restrict__ b1, const float* __restrict__ W2)
{
    __shared__ float w1t[CIN * 33];     // [d][h], row stride 33 (~33 KB)
    __shared__ float seq_s[8 * CIN];    // 8 KB
    __shared__ float s8[8 * HID];       // 1 KB
    int tid = threadIdx.x;
    int i0  = blockIdx.y * 8;
    int kc0 = blockIdx.x * 512;

    // stage W1 (coalesced LDG, 4-way-max STS)
    const float4* w1g = (const float4*)W1;
    #pragma unroll
    for (int p = 0; p < 8; p++) {
        int idx = tid + p * 256;          // 0..2047 float4s
        int h = idx >> 6, d4 = idx & 63;
        float4 v = w1g[idx];
        w1t[(d4 * 4 + 0) * 33 + h] = v.x;
        w1t[(d4 * 4 + 1) * 33 + h] = v.y;
        w1t[(d4 * 4 + 2) * 33 + h] = v.z;
        w1t[(d4 * 4 + 3) * 33 + h] = v.w;
    }
    // stage seq rows (coalesced)
    {
        const float4* sg = (const float4*)(seq + (size_t)i0 * CIN);
        float4* ss4 = (float4*)seq_s;
        #pragma unroll
        for (int p = 0; p < 2; p++) ss4[tid + p * 256] = sg[tid + p * 256];
    }
    __syncthreads();

    // part 1: s8. warp w -> i = w, lane -> h.
    {
        int w = tid >> 5, h = tid & 31;
        float acc = b1[h];
        const float4* sv4 = (const float4*)(seq_s + w * CIN);
        #pragma unroll 16
        for (int d4 = 0; d4 < 64; d4++) {
            float4 sv = sv4[d4];                     // uniform -> broadcast
            acc += sv.x * w1t[(d4 * 4 + 0) * 33 + h];
            acc += sv.y * w1t[(d4 * 4 + 1) * 33 + h];
            acc += sv.z * w1t[(d4 * 4 + 2) * 33 + h];
            acc += sv.w * w1t[(d4 * 4 + 3) * 33 + h];
        }
        s8[w * HID + h] = acc;
        if (blockIdx.x == 0) g_s[(size_t)(i0 + w) * HID + h] = acc;
    }
    __syncthreads();

    // part 2: tmp for this kc quarter.
    const float4* s84 = (const float4*)s8;
    #pragma unroll
    for (int p = 0; p < 2; p++) {
        int kc = kc0 + tid + p * 256;
        const float4* wr = (const float4*)(W2 + (size_t)kc * 32);
        float4 w[8];
        #pragma unroll
        for (int q = 0; q < 8; q++) w[q] = wr[q];
        #pragma unroll
        for (int i = 0; i < 8; i++) {
            float acc = 0.f;
            #pragma unroll
            for (int q = 0; q < 8; q++) {
                float4 sv = s84[i * 8 + q];          // uniform -> broadcast
                acc += sv.x * w[q].x + sv.y * w[q].y + sv.z * w[q].z + sv.w * w[q].w;
            }
            g_tmp[(size_t)(i0 + i) * 2048 + kc] = acc;
        }
    }
}

// ============================================================
// K3: out[i][j][k] = sum_c tmp[i][k][c]*s[j][c] + b2[k] + pair[i][j][k]
// grid (4, 512): blockIdx.y = i, blockIdx.x = jt (j-tile of 128).
// 128 threads; smem 56 KB -> 4 blocks/SM. Staging LDGs first, then
// cp.async pair prefetch (single L1tex FIFO), STS, compute, wait, epilogue.
// Split-k: thread tk owns k in {tk*4..+3} u {32+tk*4..+3} -> every LDS.128
// idx%8 == tk (conflict-free). Output stores use .cs streaming hint.
// ============================================================
__global__ __launch_bounds__(128, 4) void k3_main(
    const float* __restrict__ pair_rep, const float* __restrict__ b2,
    float* __restrict__ out)
{
    extern __shared__ float dyn[];
    float* pair_sm = dyn;                  // 128*64 = 8192 f (32 KB)
    float* s_sm    = dyn + 8192;           // [c][j] 32*128 = 4096 f (16 KB)
    float* tmp_sm  = dyn + 8192 + 4096;    // [c][k] 32*64  = 2048 f (8 KB)

    int tid = threadIdx.x;
    int i  = blockIdx.y;
    int jt = blockIdx.x;
    int tk = tid & 7;
    int tj = tid >> 3;

    // ---- phase 1: staging LDGs (issued before cp.async: L1tex FIFO) ----
    float4 sreg[8];
    {
        const float4* sr = (const float4*)(g_s + (size_t)(jt * 128 + tid) * 32);
        #pragma unroll
        for (int q = 0; q < 8; q++) sreg[q] = __ldg(sr + q);
    }
    float4 treg[8];
    if (tid < 64) {
        const float4* tr = (const float4*)(g_tmp + (size_t)i * 2048 + (size_t)tid * 32);
        #pragma unroll
        for (int q = 0; q < 8; q++) treg[q] = __ldg(tr + q);
    }
    const float4* b24 = (const float4*)b2;
    float4 bz0 = b24[tk], bz1 = b24[8 + tk];

    // ---- phase 2: async pair tile prefetch (fire & forget) ----
    {
        const float4* psrc = (const float4*)(pair_rep + (((size_t)i * 512 + (size_t)jt * 128) * 64));
        unsigned int pdst = (unsigned int)__cvta_generic_to_shared(pair_sm);
        #pragma unroll
        for (int q = 0; q < 16; q++) {
            int t = tid + q * 128;
            asm volatile("cp.async.cg.shared.global [%0], [%1], 16;"
                         :: "r"(pdst + t * 16), "l"(psrc + t));
        }
        asm volatile("cp.async.commit_group;");
    }

    // ---- phase 3: STS transposed staging ----
    #pragma unroll
    for (int q = 0; q < 8; q++) {
        s_sm[(q * 4 + 0) * 128 + tid] = sreg[q].x;
        s_sm[(q * 4 + 1) * 128 + tid] = sreg[q].y;
        s_sm[(q * 4 + 2) * 128 + tid] = sreg[q].z;
        s_sm[(q * 4 + 3) * 128 + tid] = sreg[q].w;
    }
    if (tid < 64) {
        #pragma unroll
        for (int q = 0; q < 8; q++) {
            tmp_sm[(q * 4 + 0) * 64 + tid] = treg[q].x;
            tmp_sm[(q * 4 + 1) * 64 + tid] = treg[q].y;
            tmp_sm[(q * 4 + 2) * 64 + tid] = treg[q].z;
            tmp_sm[(q * 4 + 3) * 64 + tid] = treg[q].w;
        }
    }
    __syncthreads();

    unsigned long long acc[8][4];
    #pragma unroll
    for (int a = 0; a < 8; a++)
        #pragma unroll
        for (int b = 0; b < 4; b++) acc[a][b] = 0ull;

    const float4* t4 = (const float4*)tmp_sm;   // row = 16 float4
    const float4* s4 = (const float4*)s_sm;     // row = 32 float4

    #pragma unroll 4
    for (int c = 0; c < 32; c++) {
        float4 ta = t4[c * 16 + tk];            // k = tk*4..+3
        float4 tb = t4[c * 16 + 8 + tk];        // k = 32+tk*4..+3
        unsigned long long tp0 = pk2(ta.x, ta.y);
        unsigned long long tp1 = pk2(ta.z, ta.w);
        unsigned long long tp2 = pk2(tb.x, tb.y);
        unsigned long long tp3 = pk2(tb.z, tb.w);
        float4 sa = s4[c * 32 + tj * 2];
        float4 sb = s4[c * 32 + tj * 2 + 1];
        float sv[8] = {sa.x, sa.y, sa.z, sa.w, sb.x, sb.y, sb.z, sb.w};
        #pragma unroll
        for (int jj = 0; jj < 8; jj++) {
            unsigned long long sd = pk2(sv[jj], sv[jj]);
            acc[jj][0] = ffma2(sd, tp0, acc[jj][0]);
            acc[jj][1] = ffma2(sd, tp1, acc[jj][1]);
            acc[jj][2] = ffma2(sd, tp2, acc[jj][2]);
            acc[jj][3] = ffma2(sd, tp3, acc[jj][3]);
        }
    }

    // ---- wait for pair tile, fused epilogue with streaming stores ----
    asm volatile("cp.async.wait_group 0;");
    __syncthreads();

    const float4* pr4 = (const float4*)pair_sm;
    #pragma unroll
    for (int jj = 0; jj < 8; jj++) {
        int jloc = tj * 8 + jj;
        float4 p0 = pr4[jloc * 16 + tk];        // idx%8 == tk -> conflict-free
        float4 p1 = pr4[jloc * 16 + 8 + tk];
        float x0, x1, x2, x3, x4, x5, x6, x7;
        upk2(acc[jj][0], x0, x1);
        upk2(acc[jj][1], x2, x3);
        upk2(acc[jj][2], x4, x5);
        upk2(acc[jj][3], x6, x7);
        float4 o0 = make_float4(x0 + p0.x + bz0.x, x1 + p0.y + bz0.y,
                                x2 + p0.z + bz0.z, x3 + p0.w + bz0.w);
        float4 o1 = make_float4(x4 + p1.x + bz1.x, x5 + p1.y + bz1.y,
                                x6 + p1.z + bz1.z, x7 + p1.w + bz1.w);
        size_t base = (((size_t)i * 512 + (size_t)(jt * 128 + jloc)) * 64);
        float4* op = (float4*)(out + base);
        __stcs(op + tk, o0);
        __stcs(op + 8 + tk, o1);
    }
}

// ============================================================
// Launch. Inputs (metadata order): seq, pair_rep, W1, b1, W2, b2.
// ============================================================
extern "C" void kernel_launch(void* const* d_in, const int* in_sizes, int n_in,
                              void* d_out, int out_size)
{
    const float* seq  = (const float*)d_in[0];
    const float* pair = (const float*)d_in[1];
    const float* W1   = (const float*)d_in[2];
    const float* b1   = (const float*)d_in[3];
    const float* W2   = (const float*)d_in[4];
    const float* b2   = (const float*)d_in[5];
    float* out = (float*)d_out;

    const int k3_smem = (8192 + 4096 + 2048) * 4;   // 56 KB
    cudaFuncSetAttribute(k3_main, cudaFuncAttributeMaxDynamicSharedMemorySize, k3_smem);

    dim3 g2(4, 64);
    k2_fused<<<g2, 256>>>(seq, W1, b1, W2);
    dim3 g3(4, LSEQ);
    k3_main<<<g3, 128, k3_smem>>>(pair, b2, out);
}

// round 7
// speedup vs baseline: 1.4405x; 1.1518x over previous
#include <cuda_runtime.h>

#define LSEQ 512
#define CIN  256
#define HID  32
#define PAIR 64

// Removable guard: the only new opcode vs the last passing kernel.
#define USE_L2_PREFETCH 1

// Transposed scratch layouts (producer pays scatter, consumer reads coalesced)
__device__ float g_sT[HID * LSEQ];            // g_sT[c][j]   (32 x 512)
__device__ float g_tmpT[LSEQ * HID * PAIR];   // g_tmpT[i][c][k]  (512 x 32 x 64)

// ---- packed f32x2 helpers (Blackwell FFMA2) ----
static __device__ __forceinline__ unsigned long long pk2(float a, float b) {
    unsigned long long r;
    asm("mov.b64 %0, {%1, %2};" : "=l"(r) : "f"(a), "f"(b));
    return r;
}
static __device__ __forceinline__ void upk2(unsigned long long v, float& a, float& b) {
    asm("mov.b64 {%0, %1}, %2;" : "=f"(a), "=f"(b) : "l"(v));
}
static __device__ __forceinline__ unsigned long long ffma2(
    unsigned long long a, unsigned long long b, unsigned long long c) {
    unsigned long long r;
    asm("fma.rn.f32x2 %0, %1, %2, %3;" : "=l"(r) : "l"(a), "l"(b), "l"(c));
    return r;
}

// ============================================================
// K2 (fused s + tmp): grid (4 kc-quarters, 64 i-groups), 256 threads.
//  part 1: s8[i][h] = dot(seq[i,:], W1[h,:]) + b1[h]; bx==0 publishes
//          g_sT[h][i] (transposed scatter — tiny).
//  part 2: tmp for this kc quarter, written TRANSPOSED to g_tmpT[i][c][k]
//          (scalar STGs; warp covers 64B-contiguous segments).
// ============================================================
__global__ __launch_bounds__(256) void k2_fused(
    const float* __restrict__ seq, const float* __restrict__ W1,
    const float* __restrict__ b1, const float* __restrict__ W2)
{
    __shared__ float w1t[CIN * 33];     // [d][h], stride 33 (bank-conflict-free)
    __shared__ float seq_s[8 * CIN];    // 8 KB
    __shared__ float s8[8 * HID];       // 1 KB
    int tid = threadIdx.x;
    int i0  = blockIdx.y * 8;
    int kc0 = blockIdx.x * 512;

    // stage W1 (coalesced LDG, scattered STS w/ padding)
    const float4* w1g = (const float4*)W1;
    #pragma unroll
    for (int p = 0; p < 8; p++) {
        int idx = tid + p * 256;          // 0..2047 float4s
        int h = idx >> 6, d4 = idx & 63;
        float4 v = w1g[idx];
        w1t[(d4 * 4 + 0) * 33 + h] = v.x;
        w1t[(d4 * 4 + 1) * 33 + h] = v.y;
        w1t[(d4 * 4 + 2) * 33 + h] = v.z;
        w1t[(d4 * 4 + 3) * 33 + h] = v.w;
    }
    // stage seq rows (coalesced)
    {
        const float4* sg = (const float4*)(seq + (size_t)i0 * CIN);
        float4* ss4 = (float4*)seq_s;
        #pragma unroll
        for (int p = 0; p < 2; p++) ss4[tid + p * 256] = sg[tid + p * 256];
    }
    __syncthreads();

    // part 1: s8. warp w -> i = w, lane -> h.
    {
        int w = tid >> 5, h = tid & 31;
        float acc = b1[h];
        const float4* sv4 = (const float4*)(seq_s + w * CIN);
        #pragma unroll 16
        for (int d4 = 0; d4 < 64; d4++) {
            float4 sv = sv4[d4];                     // uniform -> broadcast
            acc += sv.x * w1t[(d4 * 4 + 0) * 33 + h];
            acc += sv.y * w1t[(d4 * 4 + 1) * 33 + h];
            acc += sv.z * w1t[(d4 * 4 + 2) * 33 + h];
            acc += sv.w * w1t[(d4 * 4 + 3) * 33 + h];
        }
        s8[w * HID + h] = acc;
        if (blockIdx.x == 0) g_sT[(size_t)h * LSEQ + (i0 + w)] = acc;
    }
    __syncthreads();

    // part 2: tmp for this kc quarter, transposed write.
    const float4* s84 = (const float4*)s8;
    #pragma unroll
    for (int p = 0; p < 2; p++) {
        int kc = kc0 + tid + p * 256;     // kc = k*32 + c
        int k = kc >> 5, c = kc & 31;
        const float4* wr = (const float4*)(W2 + (size_t)kc * 32);
        float4 w[8];
        #pragma unroll
        for (int q = 0; q < 8; q++) w[q] = wr[q];
        #pragma unroll
        for (int i = 0; i < 8; i++) {
            float acc = 0.f;
            #pragma unroll
            for (int q = 0; q < 8; q++) {
                float4 sv = s84[i * 8 + q];          // uniform -> broadcast
                acc += sv.x * w[q].x + sv.y * w[q].y + sv.z * w[q].z + sv.w * w[q].w;
            }
            g_tmpT[(size_t)(i0 + i) * 2048 + c * 64 + k] = acc;
        }
    }
}

// ============================================================
// K3: out[i][j][k] = sum_c tmp[i][k][c]*s[j][c] + b2[k] + pair[i][j][k]
// grid (4, 512): by = i, bx = jt (j-tile of 128). 128 threads, 24 KB smem.
//  - L2 prefetch of the pair tile at block start (no regs, no L1 traffic).
//  - Staging: coalesced LDG.128 from transposed scratch + direct STS.128.
//  - Compute: split-k mapping, all LDS idx%8 == tk (conflict-free).
//  - Epilogue: direct LDG.128 pair (L2-warm) + add + streaming STG.
// ============================================================
__global__ __launch_bounds__(128, 4) void k3_main(
    const float* __restrict__ pair_rep, const float* __restrict__ b2,
    float* __restrict__ out)
{
    __shared__ float s_sm[32 * 128];    // [c][j] 16 KB
    __shared__ float tmp_sm[32 * 64];   // [c][k]  8 KB

    int tid = threadIdx.x;
    int i  = blockIdx.y;
    int jt = blockIdx.x;
    int tk = tid & 7;
    int tj = tid >> 3;

    const float* pbase = pair_rep + (((size_t)i * 512 + (size_t)jt * 128) * 64);

#if USE_L2_PREFETCH
    // ---- L2 prefetch of the 32 KB pair tile (256 lines, 2/thread) ----
    asm volatile("prefetch.global.L2 [%0];" :: "l"(pbase + (size_t)tid * 32));
    asm volatile("prefetch.global.L2 [%0];" :: "l"(pbase + (size_t)(tid + 128) * 32));
#endif

    // ---- staging: coalesced LDG + direct STS ----
    #pragma unroll
    for (int p = 0; p < 8; p++) {
        int idx = tid + p * 128;              // 0..1023 float4s
        int c = idx >> 5, j4 = idx & 31;
        float4 v = ((const float4*)(g_sT + c * LSEQ + jt * 128))[j4];
        ((float4*)(s_sm + c * 128))[j4] = v;
    }
    #pragma unroll
    for (int p = 0; p < 4; p++) {
        int idx = tid + p * 128;              // 0..511 float4s
        float4 v = ((const float4*)(g_tmpT + (size_t)i * 2048))[idx];
        ((float4*)tmp_sm)[idx] = v;
    }
    const float4* b24 = (const float4*)b2;
    float4 bz0 = b24[tk], bz1 = b24[8 + tk];
    __syncthreads();

    unsigned long long acc[8][4];
    #pragma unroll
    for (int a = 0; a < 8; a++)
        #pragma unroll
        for (int b = 0; b < 4; b++) acc[a][b] = 0ull;

    const float4* t4 = (const float4*)tmp_sm;   // row = 16 float4
    const float4* s4 = (const float4*)s_sm;     // row = 32 float4

    #pragma unroll 4
    for (int c = 0; c < 32; c++) {
        float4 ta = t4[c * 16 + tk];            // k = tk*4..+3
        float4 tb = t4[c * 16 + 8 + tk];        // k = 32+tk*4..+3
        unsigned long long tp0 = pk2(ta.x, ta.y);
        unsigned long long tp1 = pk2(ta.z, ta.w);
        unsigned long long tp2 = pk2(tb.x, tb.y);
        unsigned long long tp3 = pk2(tb.z, tb.w);
        float4 sa = s4[c * 32 + tj * 2];
        float4 sb = s4[c * 32 + tj * 2 + 1];
        float sv[8] = {sa.x, sa.y, sa.z, sa.w, sb.x, sb.y, sb.z, sb.w};
        #pragma unroll
        for (int jj = 0; jj < 8; jj++) {
            unsigned long long sd = pk2(sv[jj], sv[jj]);
            acc[jj][0] = ffma2(sd, tp0, acc[jj][0]);
            acc[jj][1] = ffma2(sd, tp1, acc[jj][1]);
            acc[jj][2] = ffma2(sd, tp2, acc[jj][2]);
            acc[jj][3] = ffma2(sd, tp3, acc[jj][3]);
        }
    }

    // ---- epilogue: direct pair LDG (L2-warm) + add + streaming stores ----
    #pragma unroll
    for (int jj = 0; jj < 8; jj++) {
        int jloc = tj * 8 + jj;
        const float4* pp = (const float4*)(pbase + (size_t)jloc * 64);
        float4 p0 = __ldg(pp + tk);
        float4 p1 = __ldg(pp + 8 + tk);
        float x0, x1, x2, x3, x4, x5, x6, x7;
        upk2(acc[jj][0], x0, x1);
        upk2(acc[jj][1], x2, x3);
        upk2(acc[jj][2], x4, x5);
        upk2(acc[jj][3], x6, x7);
        float4 o0 = make_float4(x0 + p0.x + bz0.x, x1 + p0.y + bz0.y,
                                x2 + p0.z + bz0.z, x3 + p0.w + bz0.w);
        float4 o1 = make_float4(x4 + p1.x + bz1.x, x5 + p1.y + bz1.y,
                                x6 + p1.z + bz1.z, x7 + p1.w + bz1.w);
        size_t base = (((size_t)i * 512 + (size_t)(jt * 128 + jloc)) * 64);
        float4* op = (float4*)(out + base);
        __stcs(op + tk, o0);
        __stcs(op + 8 + tk, o1);
    }
}

// ============================================================
// Launch. Inputs (metadata order): seq, pair_rep, W1, b1, W2, b2.
// ============================================================
extern "C" void kernel_launch(void* const* d_in, const int* in_sizes, int n_in,
                              void* d_out, int out_size)
{
    const float* seq  = (const float*)d_in[0];
    const float* pair = (const float*)d_in[1];
    const float* W1   = (const float*)d_in[2];
    const float* b1   = (const float*)d_in[3];
    const float* W2   = (const float*)d_in[4];
    const float* b2   = (const float*)d_in[5];
    float* out = (float*)d_out;

    dim3 g2(4, 64);
    k2_fused<<<g2, 256>>>(seq, W1, b1, W2);
    dim3 g3(4, LSEQ);
    k3_main<<<g3, 128>>>(pair, b2, out);
}

// round 10
// speedup vs baseline: 1.5217x; 1.0564x over previous
#include <cuda_runtime.h>

#define LSEQ 512
#define CIN  256
#define HID  32
#define PAIR 64

// Transposed scratch (producer pays transpose, consumer reads coalesced)
__device__ float g_sT[HID * LSEQ];            // g_sT[c][j]
__device__ float g_tmpT[LSEQ * HID * PAIR];   // g_tmpT[i][c][k]

// ---- packed f32x2 helpers (Blackwell FFMA2) ----
static __device__ __forceinline__ unsigned long long pk2(float a, float b) {
    unsigned long long r;
    asm("mov.b64 %0, {%1, %2};" : "=l"(r) : "f"(a), "f"(b));
    return r;
}
static __device__ __forceinline__ void upk2(unsigned long long v, float& a, float& b) {
    asm("mov.b64 {%0, %1}, %2;" : "=f"(a), "=f"(b) : "l"(v));
}
static __device__ __forceinline__ unsigned long long ffma2(
    unsigned long long a, unsigned long long b, unsigned long long c) {
    unsigned long long r;
    asm("fma.rn.f32x2 %0, %1, %2, %3;" : "=l"(r) : "l"(a), "l"(b), "l"(c));
    return r;
}

// ============================================================
// K2: grid (2 kc-halves, 64 i-groups), 256 threads, dynamic smem.
//  region0 [0, 8448):      w1t [d][h] stride-33, then per-pl W2 chunk [row][33]
//  region1 [8448, 16896):  seq_s (phase A) / buf[i][k_half][c] stride-33 (phase B)
//  part 1: s8[i][h] = seq[i,:].W1[h,:] + b1 (4-acc ILP); bx==0 publishes g_sT.
//  part 2: 4 pl-chunks: stage 256 W2 rows coalesced (conflict-free STS),
//          conflict-free scalar LDS row reads, dot vs s8, buf (conflict-free).
//  final:  buf -> g_tmpT as fully coalesced float4 STGs.
// ============================================================
__global__ __launch_bounds__(256) void k2_fused(
    const float* __restrict__ seq, const float* __restrict__ W1,
    const float* __restrict__ b1, const float* __restrict__ W2)
{
    extern __shared__ float sm[];
    float* region0 = sm;            // 8448 floats
    float* region1 = sm + 8448;     // 8448 floats
    __shared__ float s8[8 * HID];   // 1 KB

    int tid = threadIdx.x;
    int bx  = blockIdx.x;           // kc half: k in [bx*32, bx*32+32)
    int i0  = blockIdx.y * 8;

    // ---- phase A: stage W1 transposed [d][h] stride 33 + seq rows ----
    {
        const float4* w1g = (const float4*)W1;
        #pragma unroll
        for (int p = 0; p < 8; p++) {
            int idx = tid + p * 256;      // 0..2047 float4s
            int h = idx >> 6, d4 = idx & 63;
            float4 v = w1g[idx];
            region0[(d4 * 4 + 0) * 33 + h] = v.x;
            region0[(d4 * 4 + 1) * 33 + h] = v.y;
            region0[(d4 * 4 + 2) * 33 + h] = v.z;
            region0[(d4 * 4 + 3) * 33 + h] = v.w;
        }
        const float4* sg = (const float4*)(seq + (size_t)i0 * CIN);
        float4* ss4 = (float4*)region1;
        #pragma unroll
        for (int p = 0; p < 2; p++) ss4[tid + p * 256] = sg[tid + p * 256];
    }
    __syncthreads();

    // ---- part 1: s8 (warp w -> i, lane -> h), 4 independent accumulators ----
    {
        int w = tid >> 5, h = tid & 31;
        float a0 = b1[h], a1 = 0.f, a2 = 0.f, a3 = 0.f;
        const float4* sv4 = (const float4*)(region1 + w * CIN);
        #pragma unroll 16
        for (int d4 = 0; d4 < 64; d4++) {
            float4 sv = sv4[d4];                       // uniform -> broadcast
            a0 += sv.x * region0[(d4 * 4 + 0) * 33 + h];
            a1 += sv.y * region0[(d4 * 4 + 1) * 33 + h];
            a2 += sv.z * region0[(d4 * 4 + 2) * 33 + h];
            a3 += sv.w * region0[(d4 * 4 + 3) * 33 + h];
        }
        float acc = (a0 + a1) + (a2 + a3);
        s8[tid] = acc;
        if (bx == 0) g_sT[(size_t)h * LSEQ + (i0 + w)] = acc;
    }
    __syncthreads();

    // ---- part 2: 4 pl-chunks of 256 kc rows each ----
    const float4* s84 = (const float4*)s8;
    #pragma unroll 1
    for (int pl = 0; pl < 4; pl++) {
        int p_abs = bx * 4 + pl;
        // stage 256 W2 rows [kc_local][33]: coalesced LDG, conflict-free STS
        {
            const float4* w2g = (const float4*)(W2 + (size_t)p_abs * 256 * 32);
            #pragma unroll
            for (int q = 0; q < 8; q++) {
                int idx = tid + q * 256;          // 0..2047 float4s
                int r = idx >> 3, f4 = idx & 7;
                float4 v = w2g[idx];
                region0[r * 33 + f4 * 4 + 0] = v.x;
                region0[r * 33 + f4 * 4 + 1] = v.y;
                region0[r * 33 + f4 * 4 + 2] = v.z;
                region0[r * 33 + f4 * 4 + 3] = v.w;
            }
        }
        __syncthreads();

        // each thread: one kc row; conflict-free scalar LDS into registers
        {
            int kc_local = tid;
            int c = (p_abs * 256 + tid) & 31;
            int k_half = pl * 8 + (tid >> 5);
            float w_[32];
            #pragma unroll
            for (int e = 0; e < 32; e++) w_[e] = region0[kc_local * 33 + e];
            #pragma unroll
            for (int i = 0; i < 8; i++) {
                float c0 = 0.f, c1 = 0.f, c2 = 0.f, c3 = 0.f;
                #pragma unroll
                for (int q = 0; q < 8; q++) {
                    float4 sv = s84[i * 8 + q];   // uniform -> broadcast
                    c0 += sv.x * w_[q * 4 + 0];
                    c1 += sv.y * w_[q * 4 + 1];
                    c2 += sv.z * w_[q * 4 + 2];
                    c3 += sv.w * w_[q * 4 + 3];
                }
                // buf[i][k_half][c], k-stride 33 -> bank (k_half + c)%32: conflict-free
                region1[i * 1056 + k_half * 33 + c] = (c0 + c1) + (c2 + c3);
            }
        }
        __syncthreads();
    }

    // ---- final: buf -> g_tmpT[i][c][bx*32..+31], fully coalesced float4 STG ----
    #pragma unroll
    for (int q = 0; q < 8; q++) {
        int f = tid + q * 256;            // 0..2047 float4s
        int r = f >> 3, f4 = f & 7;       // r = (i, c) row, f4 = k quarter
        int i = r >> 5, c = r & 31;
        float4 v;
        v.x = region1[i * 1056 + (f4 * 4 + 0) * 33 + c];
        v.y = region1[i * 1056 + (f4 * 4 + 1) * 33 + c];
        v.z = region1[i * 1056 + (f4 * 4 + 2) * 33 + c];
        v.w = region1[i * 1056 + (f4 * 4 + 3) * 33 + c];
        *(float4*)(g_tmpT + (size_t)(i0 + i) * 2048 + c * 64 + bx * 32 + f4 * 4) = v;
    }
}

// ============================================================
// K3 (byte-identical to the R7-passing version, 32.7 us):
// out[i][j][k] = sum_c tmp[i][k][c]*s[j][c] + b2[k] + pair[i][j][k]
// grid (4, 512): by = i, bx = jt (j-tile of 128). 128 threads, 24 KB smem.
// ============================================================
__global__ __launch_bounds__(128, 4) void k3_main(
    const float* __restrict__ pair_rep, const float* __restrict__ b2,
    float* __restrict__ out)
{
    __shared__ float s_sm[32 * 128];    // [c][j] 16 KB
    __shared__ float tmp_sm[32 * 64];   // [c][k]  8 KB

    int tid = threadIdx.x;
    int i  = blockIdx.y;
    int jt = blockIdx.x;
    int tk = tid & 7;
    int tj = tid >> 3;

    const float* pbase = pair_rep + (((size_t)i * 512 + (size_t)jt * 128) * 64);

    // ---- L2 prefetch of the 32 KB pair tile (256 lines, 2/thread) ----
    asm volatile("prefetch.global.L2 [%0];" :: "l"(pbase + (size_t)tid * 32));
    asm volatile("prefetch.global.L2 [%0];" :: "l"(pbase + (size_t)(tid + 128) * 32));

    // ---- staging: coalesced LDG + direct STS ----
    #pragma unroll
    for (int p = 0; p < 8; p++) {
        int idx = tid + p * 128;              // 0..1023 float4s
        int c = idx >> 5, j4 = idx & 31;
        float4 v = ((const float4*)(g_sT + c * LSEQ + jt * 128))[j4];
        ((float4*)(s_sm + c * 128))[j4] = v;
    }
    #pragma unroll
    for (int p = 0; p < 4; p++) {
        int idx = tid + p * 128;              // 0..511 float4s
        float4 v = ((const float4*)(g_tmpT + (size_t)i * 2048))[idx];
        ((float4*)tmp_sm)[idx] = v;
    }
    const float4* b24 = (const float4*)b2;
    float4 bz0 = b24[tk], bz1 = b24[8 + tk];
    __syncthreads();

    unsigned long long acc[8][4];
    #pragma unroll
    for (int a = 0; a < 8; a++)
        #pragma unroll
        for (int b = 0; b < 4; b++) acc[a][b] = 0ull;

    const float4* t4 = (const float4*)tmp_sm;   // row = 16 float4
    const float4* s4 = (const float4*)s_sm;     // row = 32 float4

    #pragma unroll 4
    for (int c = 0; c < 32; c++) {
        float4 ta = t4[c * 16 + tk];            // k = tk*4..+3
        float4 tb = t4[c * 16 + 8 + tk];        // k = 32+tk*4..+3
        unsigned long long tp0 = pk2(ta.x, ta.y);
        unsigned long long tp1 = pk2(ta.z, ta.w);
        unsigned long long tp2 = pk2(tb.x, tb.y);
        unsigned long long tp3 = pk2(tb.z, tb.w);
        float4 sa = s4[c * 32 + tj * 2];
        float4 sb = s4[c * 32 + tj * 2 + 1];
        float sv[8] = {sa.x, sa.y, sa.z, sa.w, sb.x, sb.y, sb.z, sb.w};
        #pragma unroll
        for (int jj = 0; jj < 8; jj++) {
            unsigned long long sd = pk2(sv[jj], sv[jj]);
            acc[jj][0] = ffma2(sd, tp0, acc[jj][0]);
            acc[jj][1] = ffma2(sd, tp1, acc[jj][1]);
            acc[jj][2] = ffma2(sd, tp2, acc[jj][2]);
            acc[jj][3] = ffma2(sd, tp3, acc[jj][3]);
        }
    }

    // ---- epilogue: direct pair LDG (L2-warm) + add + streaming stores ----
    #pragma unroll
    for (int jj = 0; jj < 8; jj++) {
        int jloc = tj * 8 + jj;
        const float4* pp = (const float4*)(pbase + (size_t)jloc * 64);
        float4 p0 = __ldg(pp + tk);
        float4 p1 = __ldg(pp + 8 + tk);
        float x0, x1, x2, x3, x4, x5, x6, x7;
        upk2(acc[jj][0], x0, x1);
        upk2(acc[jj][1], x2, x3);
        upk2(acc[jj][2], x4, x5);
        upk2(acc[jj][3], x6, x7);
        float4 o0 = make_float4(x0 + p0.x + bz0.x, x1 + p0.y + bz0.y,
                                x2 + p0.z + bz0.z, x3 + p0.w + bz0.w);
        float4 o1 = make_float4(x4 + p1.x + bz1.x, x5 + p1.y + bz1.y,
                                x6 + p1.z + bz1.z, x7 + p1.w + bz1.w);
        size_t base = (((size_t)i * 512 + (size_t)(jt * 128 + jloc)) * 64);
        float4* op = (float4*)(out + base);
        __stcs(op + tk, o0);
        __stcs(op + 8 + tk, o1);
    }
}

// ============================================================
// Launch. Inputs (metadata order): seq, pair_rep, W1, b1, W2, b2.
// ============================================================
extern "C" void kernel_launch(void* const* d_in, const int* in_sizes, int n_in,
                              void* d_out, int out_size)
{
    const float* seq  = (const float*)d_in[0];
    const float* pair = (const float*)d_in[1];
    const float* W1   = (const float*)d_in[2];
    const float* b1   = (const float*)d_in[3];
    const float* W2   = (const float*)d_in[4];
    const float* b2   = (const float*)d_in[5];
    float* out = (float*)d_out;

    const int k2_smem = (8448 + 8448) * 4;   // 67.6 KB
    cudaFuncSetAttribute(k2_fused, cudaFuncAttributeMaxDynamicSharedMemorySize, k2_smem);

    dim3 g2(2, 64);
    k2_fused<<<g2, 256, k2_smem>>>(seq, W1, b1, W2);
    dim3 g3(4, LSEQ);
    k3_main<<<g3, 128>>>(pair, b2, out);
}